// round 12
// baseline (speedup 1.0000x reference)
#include <cuda_runtime.h>

// Problem constants
#define B_      128
#define D_      128
#define NROWS   600000
#define KP1     4097          // K+1
#define INV_T   (1.0f / 0.07f)
#define NENT    (B_ * KP1)    // 524,416 (b,k) entries

#define SLOTS    10
#define OVF_CAP  16384

#define MAIN_BLOCKS 4096      // multi-wave: HW rebalances non-uniform warp work

// Scratch. Zero at module load. Replay hygiene:
//   - g_count, g_ovf_n : re-zeroed by finalize_kernel (after copy_dot consumed them)
//   - g_sum_l/g_sum_ab : re-zeroed by build_kernel of the NEXT launch
__device__ int      g_count[NROWS];
__device__ unsigned g_slots[(size_t)NROWS * SLOTS];
__device__ unsigned g_ovf[OVF_CAP];
__device__ int      g_ovf_n;
__device__ double   g_sum_l;
__device__ double   g_sum_ab;

// ---------------------------------------------------------------------------
// 1) Build inverted index: row -> packed (b<<13 | k). g_count pre-zeroed.
//    LSU-issue-bound (~3 LSU ops/entry at the ~1.82cyc/op SM floor).
__global__ __launch_bounds__(256) void build_kernel(const int* __restrict__ idx) {
    const int tid = blockIdx.x * 256 + threadIdx.x;
    if (tid == 0) { g_sum_l = 0.0; g_sum_ab = 0.0; }   // reset for this launch
    if (tid >= NENT) return;
    const int b = tid / KP1;
    const int k = tid - b * KP1;
    const int r = idx[tid];
    const unsigned ent = ((unsigned)b << 13) | (unsigned)k;
    const int c = atomicAdd(&g_count[r], 1);
    if (c < SLOTS) {
        g_slots[(size_t)r * SLOTS + c] = ent;
    } else {
        const int o = atomicAdd(&g_ovf_n, 1);
        if (o < OVF_CAP) g_ovf[o] = ent;
    }
}

// ---------------------------------------------------------------------------
// Warp helper: dot both banks' row vectors against (l, ab), exp, store, accum.
__device__ __forceinline__ void process_entry(
    unsigned ent, const float4& a, const float4& c,
    const float* __restrict__ l, const float* __restrict__ ab,
    float* __restrict__ out_l, float* __restrict__ out_ab,
    int lane, double& s_l, double& s_ab)
{
    const int b = ent >> 13;
    const int k = ent & 8191;
    const float4 av = reinterpret_cast<const float4*>(ab + b * D_)[lane];
    const float4 lv = reinterpret_cast<const float4*>(l  + b * D_)[lane];

    float dab = a.x * av.x + a.y * av.y + a.z * av.z + a.w * av.w;
    float dl  = c.x * lv.x + c.y * lv.y + c.z * lv.z + c.w * lv.w;
    #pragma unroll
    for (int off = 16; off > 0; off >>= 1) {
        dab += __shfl_xor_sync(0xffffffffu, dab, off);
        dl  += __shfl_xor_sync(0xffffffffu, dl,  off);
    }
    if (lane == 0) {
        const float el  = __expf(dl  * INV_T);
        const float eab = __expf(dab * INV_T);
        out_l [b * KP1 + k] = el;
        out_ab[b * KP1 + k] = eab;
        s_l  += (double)el;
        s_ab += (double)eab;
    }
}

// ---------------------------------------------------------------------------
// 2) Fused: overflow drain + streaming bank copy + inverted-gather dot/exp.
//    Simple 1-row-per-warp loop (BW-bound; proven optimal shape). All
//    single-use metadata reads use streaming hints to protect L2 for the copy.
__global__ __launch_bounds__(256) void copy_dot_kernel(
    const float* __restrict__ l,
    const float* __restrict__ ab,
    const int*   __restrict__ idx,
    const float* __restrict__ mem_l,
    const float* __restrict__ mem_ab,
    float* __restrict__ out)
{
    float* out_l   = out;                              // [B, KP1] raw exp
    float* out_ab  = out + (size_t)B_ * KP1;
    float* out_ml  = out + (size_t)2 * B_ * KP1;       // [N, D]
    float* out_mab = out_ml + (size_t)NROWS * D_;

    const int lane   = threadIdx.x & 31;
    const int warp   = threadIdx.x >> 5;
    const int warp_g = (blockIdx.x * blockDim.x + threadIdx.x) >> 5;
    const int nwarps = (gridDim.x * blockDim.x) >> 5;

    double s_l = 0.0, s_ab = 0.0;

    // --- Overflow drain (expected ~0 entries) ---
    {
        const int novf = min(g_ovf_n, OVF_CAP);
        for (int i = warp_g; i < novf; i += nwarps) {
            const unsigned ent = g_ovf[i];
            const int b = ent >> 13;
            const int k = ent & 8191;
            const int r = idx[b * KP1 + k];
            const float4 a = reinterpret_cast<const float4*>(mem_l  + (size_t)r * D_)[lane];
            const float4 c = reinterpret_cast<const float4*>(mem_ab + (size_t)r * D_)[lane];
            process_entry(ent, a, c, l, ab, out_l, out_ab, lane, s_l, s_ab);
        }
    }

    // --- Streaming copy + fused dots (1 row per warp iteration) ---
    for (int r = warp_g; r < NROWS; r += nwarps) {
        const float4 a = __ldcs(reinterpret_cast<const float4*>(mem_l  + (size_t)r * D_) + lane);
        const float4 c = __ldcs(reinterpret_cast<const float4*>(mem_ab + (size_t)r * D_) + lane);
        __stcs(reinterpret_cast<float4*>(out_ml  + (size_t)r * D_) + lane, a);
        __stcs(reinterpret_cast<float4*>(out_mab + (size_t)r * D_) + lane, c);

        int n = __ldcs(&g_count[r]);
        if (n > SLOTS) n = SLOTS;
        for (int e = 0; e < n; e++) {
            const unsigned ent = __ldcs(&g_slots[(size_t)r * SLOTS + e]);
            process_entry(ent, a, c, l, ab, out_l, out_ab, lane, s_l, s_ab);
        }
    }

    // --- Block reduction of partial sums, one atomicAdd pair per block ---
    __shared__ double sh_l[8], sh_ab[8];
    if (lane == 0) { sh_l[warp] = s_l; sh_ab[warp] = s_ab; }
    __syncthreads();
    if (threadIdx.x == 0) {
        double bl = 0.0, bab = 0.0;
        #pragma unroll
        for (int w = 0; w < 8; w++) { bl += sh_l[w]; bab += sh_ab[w]; }
        atomicAdd(&g_sum_l,  bl);
        atomicAdd(&g_sum_ab, bab);
    }
}

// ---------------------------------------------------------------------------
// 3) Finalize: momentum scatter-update (L2 renorm) + Z-scaling of logits +
//    re-zero g_count / g_ovf_n for the next graph replay.
//    Each scale block computes the two float scales once (thread 0, fp64 div
//    pair) and broadcasts via smem — no per-thread fp64, no cross-kernel state.
#define FIN_WORK_BLOCKS 2344   // ceil(NROWS / 256): enough to zero g_count 1:1
__global__ __launch_bounds__(256) void finalize_kernel(
    const float* __restrict__ l,
    const float* __restrict__ ab,
    const int*   __restrict__ y,
    const float* __restrict__ mem_l,
    const float* __restrict__ mem_ab,
    float* __restrict__ out)
{
    float* out_l   = out;
    float* out_ml  = out + (size_t)2 * B_ * KP1;
    float* out_mab = out_ml + (size_t)NROWS * D_;

    if (blockIdx.x < B_) {
        const int b  = blockIdx.x;
        const int yb = y[b];
        // Duplicate-index semantics: last writer wins (JAX scatter order).
        bool skip = false;
        for (int j = b + 1; j < B_; j++) if (y[j] == yb) skip = true;
        if (skip) return;

        const int tid  = threadIdx.x;
        const int bank = tid >> 7;      // 0: l-bank, 1: ab-bank
        const int e    = tid & 127;

        const float* mem = bank ? mem_ab : mem_l;
        const float* vec = bank ? ab      : l;
        float* outm      = bank ? out_mab : out_ml;

        const float v = mem[(size_t)yb * D_ + e] * 0.5f + vec[b * D_ + e] * 0.5f;
        float s = v * v;
        #pragma unroll
        for (int off = 16; off > 0; off >>= 1)
            s += __shfl_xor_sync(0xffffffffu, s, off);

        __shared__ float part[8];
        if ((tid & 31) == 0) part[tid >> 5] = s;
        __syncthreads();

        const float tot = part[bank * 4 + 0] + part[bank * 4 + 1]
                        + part[bank * 4 + 2] + part[bank * 4 + 3];
        outm[(size_t)yb * D_ + e] = v / sqrtf(tot);
    } else {
        const int wtid = (blockIdx.x - B_) * 256 + threadIdx.x;

        // Per-block scale computation: scale = B*KP1 / (sum * N)
        __shared__ float sh_sc[2];
        if (threadIdx.x == 0) {
            sh_sc[0] = (float)((double)B_ * (double)KP1 / (g_sum_l  * (double)NROWS));
            sh_sc[1] = (float)((double)B_ * (double)KP1 / (g_sum_ab * (double)NROWS));
        }

        // (a) zero g_count for next replay (one int per thread; no sync needed)
        if (wtid < NROWS) g_count[wtid] = 0;
        if (wtid == 0) g_ovf_n = 0;

        __syncthreads();
        const float sc_l  = sh_sc[0];
        const float sc_ab = sh_sc[1];

        // (b) scale logits: one float4 per thread, exact-size
        const size_t half4  = (size_t)B_ * KP1 / 4;       // 131,104 float4 per array
        const size_t total4 = half4 * 2;                  // 262,208 < 2344*256

        if ((size_t)wtid < total4) {
            const float sc = ((size_t)wtid < half4) ? sc_l : sc_ab;
            float4* o4 = reinterpret_cast<float4*>(out_l);
            float4 v = o4[wtid];
            v.x *= sc; v.y *= sc; v.z *= sc; v.w *= sc;
            o4[wtid] = v;
        }
    }
}

extern "C" void kernel_launch(void* const* d_in, const int* in_sizes, int n_in,
                              void* d_out, int out_size)
{
    const float* l      = (const float*)d_in[0];
    const float* ab     = (const float*)d_in[1];
    const int*   y      = (const int*)  d_in[2];
    const int*   idx    = (const int*)  d_in[3];
    const float* mem_l  = (const float*)d_in[4];
    const float* mem_ab = (const float*)d_in[5];
    float* out = (float*)d_out;

    build_kernel<<<(NENT + 255) / 256, 256>>>(idx);
    copy_dot_kernel<<<MAIN_BLOCKS, 256>>>(l, ab, idx, mem_l, mem_ab, out);
    finalize_kernel<<<B_ + FIN_WORK_BLOCKS, 256>>>(l, ab, y, mem_l, mem_ab, out);
}

// round 13
// speedup vs baseline: 1.0757x; 1.0757x over previous
#include <cuda_runtime.h>

// Problem constants
#define B_      128
#define D_      128
#define NROWS   600000
#define KP1     4097          // K+1
#define INV_T   (1.0f / 0.07f)
#define NENT    (B_ * KP1)    // 524,416 (b,k) entries

#define SLOTS    10
#define OVF_CAP  16384

#define MAIN_BLOCKS 4096      // multi-wave: HW rebalances non-uniform warp work

// Scratch. Zero at module load. Replay hygiene:
//   - g_count, g_ovf_n : re-zeroed by finalize_kernel (after copy_dot consumed them)
//   - g_sum_l/g_sum_ab : re-zeroed by build_kernel of the NEXT launch
__device__ int      g_count[NROWS];
__device__ unsigned g_slots[(size_t)NROWS * SLOTS];
__device__ unsigned g_ovf[OVF_CAP];
__device__ int      g_ovf_n;
__device__ double   g_sum_l;
__device__ double   g_sum_ab;

// ---------------------------------------------------------------------------
// 1) Build inverted index: row -> packed (b<<13 | k). g_count pre-zeroed.
//    LSU-issue-bound (~3 LSU ops/entry at the ~1.82cyc/op SM floor).
__global__ __launch_bounds__(256) void build_kernel(const int* __restrict__ idx) {
    const int tid = blockIdx.x * 256 + threadIdx.x;
    if (tid == 0) { g_sum_l = 0.0; g_sum_ab = 0.0; }   // reset for this launch
    if (tid >= NENT) return;
    const int b = tid / KP1;
    const int k = tid - b * KP1;
    const int r = idx[tid];
    const unsigned ent = ((unsigned)b << 13) | (unsigned)k;
    const int c = atomicAdd(&g_count[r], 1);
    if (c < SLOTS) {
        g_slots[(size_t)r * SLOTS + c] = ent;
    } else {
        const int o = atomicAdd(&g_ovf_n, 1);
        if (o < OVF_CAP) g_ovf[o] = ent;
    }
}

// ---------------------------------------------------------------------------
// Warp helper: dot both banks' row vectors against (l, ab), exp, store, accum.
__device__ __forceinline__ void process_entry(
    unsigned ent, const float4& a, const float4& c,
    const float* __restrict__ l, const float* __restrict__ ab,
    float* __restrict__ out_l, float* __restrict__ out_ab,
    int lane, double& s_l, double& s_ab)
{
    const int b = ent >> 13;
    const int k = ent & 8191;
    const float4 av = reinterpret_cast<const float4*>(ab + b * D_)[lane];
    const float4 lv = reinterpret_cast<const float4*>(l  + b * D_)[lane];

    float dab = a.x * av.x + a.y * av.y + a.z * av.z + a.w * av.w;
    float dl  = c.x * lv.x + c.y * lv.y + c.z * lv.z + c.w * lv.w;
    #pragma unroll
    for (int off = 16; off > 0; off >>= 1) {
        dab += __shfl_xor_sync(0xffffffffu, dab, off);
        dl  += __shfl_xor_sync(0xffffffffu, dl,  off);
    }
    if (lane == 0) {
        const float el  = __expf(dl  * INV_T);
        const float eab = __expf(dab * INV_T);
        out_l [b * KP1 + k] = el;
        out_ab[b * KP1 + k] = eab;
        s_l  += (double)el;
        s_ab += (double)eab;
    }
}

// ---------------------------------------------------------------------------
// 2) Fused: overflow drain + streaming bank copy + inverted-gather dot/exp.
//    Simple 1-row-per-warp loop (BW-bound; proven optimal shape).
__global__ __launch_bounds__(256) void copy_dot_kernel(
    const float* __restrict__ l,
    const float* __restrict__ ab,
    const int*   __restrict__ idx,
    const float* __restrict__ mem_l,
    const float* __restrict__ mem_ab,
    float* __restrict__ out)
{
    float* out_l   = out;                              // [B, KP1] raw exp
    float* out_ab  = out + (size_t)B_ * KP1;
    float* out_ml  = out + (size_t)2 * B_ * KP1;       // [N, D]
    float* out_mab = out_ml + (size_t)NROWS * D_;

    const int lane   = threadIdx.x & 31;
    const int warp   = threadIdx.x >> 5;
    const int warp_g = (blockIdx.x * blockDim.x + threadIdx.x) >> 5;
    const int nwarps = (gridDim.x * blockDim.x) >> 5;

    double s_l = 0.0, s_ab = 0.0;

    // --- Overflow drain (expected ~0 entries) ---
    {
        const int novf = min(g_ovf_n, OVF_CAP);
        for (int i = warp_g; i < novf; i += nwarps) {
            const unsigned ent = g_ovf[i];
            const int b = ent >> 13;
            const int k = ent & 8191;
            const int r = idx[b * KP1 + k];
            const float4 a = reinterpret_cast<const float4*>(mem_l  + (size_t)r * D_)[lane];
            const float4 c = reinterpret_cast<const float4*>(mem_ab + (size_t)r * D_)[lane];
            process_entry(ent, a, c, l, ab, out_l, out_ab, lane, s_l, s_ab);
        }
    }

    // --- Streaming copy + fused dots (1 row per warp iteration) ---
    for (int r = warp_g; r < NROWS; r += nwarps) {
        const float4 a = __ldcs(reinterpret_cast<const float4*>(mem_l  + (size_t)r * D_) + lane);
        const float4 c = __ldcs(reinterpret_cast<const float4*>(mem_ab + (size_t)r * D_) + lane);
        __stcs(reinterpret_cast<float4*>(out_ml  + (size_t)r * D_) + lane, a);
        __stcs(reinterpret_cast<float4*>(out_mab + (size_t)r * D_) + lane, c);

        int n = g_count[r];
        if (n > SLOTS) n = SLOTS;
        for (int e = 0; e < n; e++) {
            const unsigned ent = g_slots[(size_t)r * SLOTS + e];
            process_entry(ent, a, c, l, ab, out_l, out_ab, lane, s_l, s_ab);
        }
    }

    // --- Block reduction of partial sums, one atomicAdd pair per block ---
    __shared__ double sh_l[8], sh_ab[8];
    if (lane == 0) { sh_l[warp] = s_l; sh_ab[warp] = s_ab; }
    __syncthreads();
    if (threadIdx.x == 0) {
        double bl = 0.0, bab = 0.0;
        #pragma unroll
        for (int w = 0; w < 8; w++) { bl += sh_l[w]; bab += sh_ab[w]; }
        atomicAdd(&g_sum_l,  bl);
        atomicAdd(&g_sum_ab, bab);
    }
}

// ---------------------------------------------------------------------------
// 3) Finalize: momentum scatter-update (L2 renorm) + Z-scaling of logits +
//    re-zero g_count / g_ovf_n for the next graph replay.
//    Each scale block computes the two float scales once (thread 0, fp64 div
//    pair) and broadcasts via smem — no per-thread fp64, no cross-kernel state.
#define FIN_WORK_BLOCKS 2344   // ceil(NROWS / 256): enough to zero g_count 1:1
__global__ __launch_bounds__(256) void finalize_kernel(
    const float* __restrict__ l,
    const float* __restrict__ ab,
    const int*   __restrict__ y,
    const float* __restrict__ mem_l,
    const float* __restrict__ mem_ab,
    float* __restrict__ out)
{
    float* out_l   = out;
    float* out_ml  = out + (size_t)2 * B_ * KP1;
    float* out_mab = out_ml + (size_t)NROWS * D_;

    if (blockIdx.x < B_) {
        const int b  = blockIdx.x;
        const int yb = y[b];
        // Duplicate-index semantics: last writer wins (JAX scatter order).
        bool skip = false;
        for (int j = b + 1; j < B_; j++) if (y[j] == yb) skip = true;
        if (skip) return;

        const int tid  = threadIdx.x;
        const int bank = tid >> 7;      // 0: l-bank, 1: ab-bank
        const int e    = tid & 127;

        const float* mem = bank ? mem_ab : mem_l;
        const float* vec = bank ? ab      : l;
        float* outm      = bank ? out_mab : out_ml;

        const float v = mem[(size_t)yb * D_ + e] * 0.5f + vec[b * D_ + e] * 0.5f;
        float s = v * v;
        #pragma unroll
        for (int off = 16; off > 0; off >>= 1)
            s += __shfl_xor_sync(0xffffffffu, s, off);

        __shared__ float part[8];
        if ((tid & 31) == 0) part[tid >> 5] = s;
        __syncthreads();

        const float tot = part[bank * 4 + 0] + part[bank * 4 + 1]
                        + part[bank * 4 + 2] + part[bank * 4 + 3];
        outm[(size_t)yb * D_ + e] = v / sqrtf(tot);
    } else {
        const int wtid = (blockIdx.x - B_) * 256 + threadIdx.x;

        // Per-block scale computation: scale = B*KP1 / (sum * N)
        __shared__ float sh_sc[2];
        if (threadIdx.x == 0) {
            sh_sc[0] = (float)((double)B_ * (double)KP1 / (g_sum_l  * (double)NROWS));
            sh_sc[1] = (float)((double)B_ * (double)KP1 / (g_sum_ab * (double)NROWS));
        }

        // (a) zero g_count for next replay (one int per thread; no sync needed)
        if (wtid < NROWS) g_count[wtid] = 0;
        if (wtid == 0) g_ovf_n = 0;

        __syncthreads();
        const float sc_l  = sh_sc[0];
        const float sc_ab = sh_sc[1];

        // (b) scale logits: one float4 per thread, exact-size
        const size_t half4  = (size_t)B_ * KP1 / 4;       // 131,104 float4 per array
        const size_t total4 = half4 * 2;                  // 262,208 < 2344*256

        if ((size_t)wtid < total4) {
            const float sc = ((size_t)wtid < half4) ? sc_l : sc_ab;
            float4* o4 = reinterpret_cast<float4*>(out_l);
            float4 v = o4[wtid];
            v.x *= sc; v.y *= sc; v.z *= sc; v.w *= sc;
            o4[wtid] = v;
        }
    }
}

extern "C" void kernel_launch(void* const* d_in, const int* in_sizes, int n_in,
                              void* d_out, int out_size)
{
    const float* l      = (const float*)d_in[0];
    const float* ab     = (const float*)d_in[1];
    const int*   y      = (const int*)  d_in[2];
    const int*   idx    = (const int*)  d_in[3];
    const float* mem_l  = (const float*)d_in[4];
    const float* mem_ab = (const float*)d_in[5];
    float* out = (float*)d_out;

    build_kernel<<<(NENT + 255) / 256, 256>>>(idx);
    copy_dot_kernel<<<MAIN_BLOCKS, 256>>>(l, ab, idx, mem_l, mem_ab, out);
    finalize_kernel<<<B_ + FIN_WORK_BLOCKS, 256>>>(l, ab, y, mem_l, mem_ab, out);
}